// round 6
// baseline (speedup 1.0000x reference)
#include <cuda_runtime.h>
#include <cuda_bf16.h>

#define NS 2000
#define NH 64
#define NB 1024
#define NQ 4              // s-dimension split per batch row
#define SQ (NS / NQ)      // 500 s-rows per tile

// Scratch for rel_encoded [S, H] (no cudaMalloc allowed)
__device__ float g_rel_enc[NS * NH];

// ---------------------------------------------------------------------------
// Kernel 1: rel_enc[s,:] = mask(s) * ( relu(rel[idx,s,:] @ W1^T + b1) @ W2^T + b2 )
// 125 blocks x 256 threads; each block stages W1/W2 once and processes
// 16 rows in 4 passes (4x less weight-staging traffic than 500 blocks).
// Also zero-initializes the output buffer for the reduce kernel's atomics.
// ---------------------------------------------------------------------------
__global__ __launch_bounds__(256)
void mlp_kernel(const int* __restrict__ stock_idx,
                const float* __restrict__ rel,
                const float* __restrict__ W1,
                const float* __restrict__ b1,
                const float* __restrict__ W2,
                const float* __restrict__ b2,
                float* __restrict__ out)
{
    __shared__ float W1s[NH * 65];   // padded rows -> bank-conflict free
    __shared__ float W2s[NH * 65];
    __shared__ float rowbuf[4 * NH];
    __shared__ float hbuf[4 * NH];

    const int t = threadIdx.x;
    const int r = t >> 6;      // row-within-pass 0..3
    const int j = t & 63;      // hidden index 0..63
    const int idx = *stock_idx;

    // Zero the output (grid-stride over 1024*64 = 65536 elements)
    for (int i = blockIdx.x * 256 + t; i < NB * NH; i += gridDim.x * 256)
        out[i] = 0.0f;

    // Stage W1, W2 into shared (coalesced) — once per block
    for (int i = t; i < NH * NH; i += 256) {
        W1s[(i >> 6) * 65 + (i & 63)] = W1[i];
        W2s[(i >> 6) * 65 + (i & 63)] = W2[i];
    }
    __syncthreads();

    #pragma unroll
    for (int pass = 0; pass < 4; pass++) {
        const int s = blockIdx.x * 16 + pass * 4 + r;

        rowbuf[r * NH + j] = rel[(size_t)idx * NS * NH + (size_t)s * NH + j];
        __syncthreads();

        // layer 1
        float acc = b1[j];
        #pragma unroll 16
        for (int k = 0; k < NH; k++)
            acc = fmaf(rowbuf[r * NH + k], W1s[j * 65 + k], acc);
        hbuf[r * NH + j] = fmaxf(acc, 0.0f);
        __syncthreads();

        // layer 2
        float acc2 = b2[j];
        #pragma unroll 16
        for (int k = 0; k < NH; k++)
            acc2 = fmaf(hbuf[r * NH + k], W2s[j * 65 + k], acc2);

        if (s == idx) acc2 = 0.0f;   // exclude i == stock_idx
        g_rel_enc[s * NH + j] = acc2;
        __syncthreads();             // protect rowbuf/hbuf for next pass
    }
}

// ---------------------------------------------------------------------------
// Kernel 2: out[b,h] += sum_{s in quarter} enc[b,s,h] * rel_enc[s,h]
// grid = NB*NQ tiles (4096), Q-MAJOR bid ordering: co-resident CTAs on an SM
// share the same rel_enc quarter (128KB) -> L1-resident rel, halved LTS load.
// enc read with __ldcs (streaming, evict-first, keeps L1 for rel).
// ---------------------------------------------------------------------------
__global__ __launch_bounds__(256)
void reduce_kernel(const float4* __restrict__ enc,  // [B, S, 16] float4
                   float* __restrict__ out)         // [B, 64]
{
    const int tile = blockIdx.x;
    const int q = tile >> 10;          // s-quarter (q-major: 1024 bids share q)
    const int b = tile & 1023;         // batch row
    const int t = threadIdx.x;
    const int h16  = t & 15;           // float4 lane within hidden dim
    const int srow = t >> 4;           // 0..15

    const float4* __restrict__ encB = enc + (size_t)b * NS * (NH / 4);
    const float4* __restrict__ rel4 = (const float4*)g_rel_enc;

    const int s_base = q * SQ;
    const int s_end  = s_base + SQ;

    float4 acc = make_float4(0.f, 0.f, 0.f, 0.f);

    #pragma unroll 4
    for (int s = s_base + srow; s < s_end; s += 16) {
        const float4 e  = __ldcs(&encB[s * 16 + h16]);   // stream, don't cache
        const float4 rv = __ldg(&rel4[s * 16 + h16]);    // L1-resident
        acc.x = fmaf(e.x, rv.x, acc.x);
        acc.y = fmaf(e.y, rv.y, acc.y);
        acc.z = fmaf(e.z, rv.z, acc.z);
        acc.w = fmaf(e.w, rv.w, acc.w);
    }

    __shared__ float4 red[256];
    red[t] = acc;
    __syncthreads();

    #pragma unroll
    for (int off = 128; off >= 16; off >>= 1) {
        if (t < off) {
            float4 a = red[t], bb = red[t + off];
            a.x += bb.x; a.y += bb.y; a.z += bb.z; a.w += bb.w;
            red[t] = a;
        }
        __syncthreads();
    }

    // 64 scalar partials -> global accumulate (4 tiles hit each address)
    if (t < 64) {
        const float v = ((const float*)red)[t];
        atomicAdd(&out[b * NH + t], v);
    }
}

// ---------------------------------------------------------------------------
// Inputs (metadata order):
//   d_in[0] stock_idx            int32   [1]
//   d_in[1] encoded_states       f32     [1024, 2000, 64]
//   d_in[2] relationship_matrix  f32     [2000, 2000, 64]
//   d_in[3] W1  f32 [64,64]   d_in[4] b1 f32 [64]
//   d_in[5] W2  f32 [64,64]   d_in[6] b2 f32 [64]
// Output: f32 [1024, 64]
// ---------------------------------------------------------------------------
extern "C" void kernel_launch(void* const* d_in, const int* in_sizes, int n_in,
                              void* d_out, int out_size)
{
    const int*   stock_idx = (const int*)  d_in[0];
    const float* enc       = (const float*)d_in[1];
    const float* rel       = (const float*)d_in[2];
    const float* W1        = (const float*)d_in[3];
    const float* b1        = (const float*)d_in[4];
    const float* W2        = (const float*)d_in[5];
    const float* b2        = (const float*)d_in[6];
    float* out = (float*)d_out;

    mlp_kernel<<<NS / 16, 256>>>(stock_idx, rel, W1, b1, W2, b2, out);
    reduce_kernel<<<NB * NQ, 256>>>((const float4*)enc, out);
}